// round 2
// baseline (speedup 1.0000x reference)
#include <cuda_runtime.h>
#include <math.h>

// ---------------- scratch (device globals; no cudaMalloc allowed) ----------
#define B_   32
#define HW_  4096           // 64*64
#define C1O  64
#define C2O  128

__device__ float g_h1c[(size_t)B_ * HW_ * C1O];        // channel-last h1: [b][h][w][c]
__device__ float g_off2[(size_t)B_ * 18 * HW_];        // offsets layer2
__device__ float g_partial[(size_t)4096 * C2O];        // per-block pooled partials
__device__ float g_wT[576 * 128];                      // transposed conv2 weights [e][co]

// ---------------- packed f32x2 helpers --------------------------------------
typedef unsigned long long ull;

__device__ __forceinline__ ull fma2(ull a, ull b, ull c) {
    ull d;
    asm("fma.rn.f32x2 %0, %1, %2, %3;" : "=l"(d) : "l"(a), "l"(b), "l"(c));
    return d;
}
__device__ __forceinline__ ull add2(ull a, ull b) {
    ull d;
    asm("add.rn.f32x2 %0, %1, %2;" : "=l"(d) : "l"(a), "l"(b));
    return d;
}
__device__ __forceinline__ ull dup2(float v) {
    ull d;
    unsigned r = __float_as_uint(v);
    asm("mov.b64 %0, {%1, %1};" : "=l"(d) : "r"(r));
    return d;
}
__device__ __forceinline__ float2 unpack2(ull v) {
    unsigned lo, hi;
    asm("mov.b64 {%0, %1}, %2;" : "=r"(lo), "=r"(hi) : "l"(v));
    return make_float2(__uint_as_float(lo), __uint_as_float(hi));
}

// ---------------- K0: transpose conv2 weights -------------------------------
__global__ void k0_transpose(const float* __restrict__ cw)
{
    int idx = blockIdx.x * 256 + threadIdx.x;
    if (idx >= 576 * 128) return;
    int co = idx & 127, e = idx >> 7;
    g_wT[e * 128 + co] = cw[co * 576 + e];
}

// ---------------- K1: offset1 conv + deform conv1 + bn1 + relu -------------
__global__ void __launch_bounds__(128)
k1_layer1(const float* __restrict__ x,
          const float* __restrict__ ow, const float* __restrict__ ob,
          const float* __restrict__ cw, const float* __restrict__ cb,
          const float* __restrict__ g1, const float* __restrict__ be1,
          const float* __restrict__ m1, const float* __restrict__ v1)
{
    __shared__ float s_ow[486];     // 18*27
    __shared__ float s_cw[1728];    // 64*27
    __shared__ float s_ob[18];
    __shared__ float s_scale[64], s_bias[64];
    __shared__ float s_out[128 * 65];

    int tid = threadIdx.x;
    for (int i = tid; i < 486; i += 128)  s_ow[i] = ow[i];
    for (int i = tid; i < 1728; i += 128) s_cw[i] = cw[i];
    if (tid < 18) s_ob[tid] = ob[tid];
    if (tid < 64) {
        float sc = g1[tid] * rsqrtf(v1[tid] + 1e-5f);
        s_scale[tid] = sc;
        s_bias[tid]  = be1[tid] + (cb[tid] - m1[tid]) * sc;
    }
    __syncthreads();

    int lin = blockIdx.x * 128 + tid;
    int b = lin >> 12, hw = lin & 4095, h = hw >> 6, w = hw & 63;
    const float* xb = x + (size_t)b * 3 * 4096;

    float xwin[27];
    #pragma unroll
    for (int ci = 0; ci < 3; ci++)
        #pragma unroll
        for (int kh = 0; kh < 3; kh++)
            #pragma unroll
            for (int kw = 0; kw < 3; kw++) {
                int yy = h + kh - 1, xx = w + kw - 1;
                float val = 0.f;
                if (yy >= 0 && yy < 64 && xx >= 0 && xx < 64)
                    val = xb[ci * 4096 + yy * 64 + xx];
                xwin[ci * 9 + kh * 3 + kw] = val;
            }

    float off[18];
    #pragma unroll
    for (int c = 0; c < 18; c++) {
        float a = s_ob[c];
        #pragma unroll
        for (int j = 0; j < 27; j++) a += xwin[j] * s_ow[c * 27 + j];
        off[c] = a;
    }

    float v[27];
    #pragma unroll
    for (int tap = 0; tap < 9; tap++) {
        float py = (float)(h + tap / 3 - 1) + off[tap * 2];
        float px = (float)(w + tap % 3 - 1) + off[tap * 2 + 1];
        float y0f = floorf(py), x0f = floorf(px);
        int y0 = (int)y0f, x0 = (int)x0f;
        float wy = py - y0f, wx = px - x0f;
        float w00 = (1.f - wy) * (1.f - wx), w01 = (1.f - wy) * wx;
        float w10 = wy * (1.f - wx),         w11 = wy * wx;
        bool vy0 = ((unsigned)y0 < 64u), vy1 = ((unsigned)(y0 + 1) < 64u);
        bool vx0 = ((unsigned)x0 < 64u), vx1 = ((unsigned)(x0 + 1) < 64u);
        long long i00 = (long long)y0 * 64 + x0;
        #pragma unroll
        for (int ci = 0; ci < 3; ci++) {
            const float* p = xb + ci * 4096;
            float c00 = (vy0 && vx0) ? p[i00]      : 0.f;
            float c01 = (vy0 && vx1) ? p[i00 + 1]  : 0.f;
            float c10 = (vy1 && vx0) ? p[i00 + 64] : 0.f;
            float c11 = (vy1 && vx1) ? p[i00 + 65] : 0.f;
            v[ci * 9 + tap] = c00 * w00 + c01 * w01 + c10 * w10 + c11 * w11;
        }
    }

    #pragma unroll 4
    for (int co = 0; co < 64; co++) {
        float a = 0.f;
        #pragma unroll
        for (int j = 0; j < 27; j++) a += v[j] * s_cw[co * 27 + j];
        float val = a * s_scale[co] + s_bias[co];
        s_out[tid * 65 + co] = fmaxf(val, 0.f);
    }
    __syncthreads();

    size_t base = (size_t)blockIdx.x * 128 * 64;
    for (int i = tid; i < 8192; i += 128)
        g_h1c[base + i] = s_out[(i >> 6) * 65 + (i & 63)];
}

// ---------------- K2: offset2 conv (64 -> 18), f32x2 -------------------------
// 256 threads, 64 locations per block, 4 threads per location (16 ch each)
__global__ void __launch_bounds__(256)
k2_off2(const float* __restrict__ w2, const float* __restrict__ b2)
{
    __shared__ float s_w[576 * 20];   // transposed, padded: [(ci*9+pos)][o(20)]
    __shared__ float s_b[18];
    int tid = threadIdx.x;
    for (int i = tid; i < 18 * 576; i += 256) {
        int o = i / 576, cp = i % 576;
        s_w[cp * 20 + o] = w2[i];
    }
    for (int i = tid; i < 576; i += 256) { s_w[i * 20 + 18] = 0.f; s_w[i * 20 + 19] = 0.f; }
    if (tid < 18) s_b[tid] = b2[tid];
    __syncthreads();

    int loc_l = tid >> 2, q = tid & 3;
    int lin = blockIdx.x * 64 + loc_l;
    int b = lin >> 12, hw = lin & 4095, h = hw >> 6, w = hw & 63;
    const float* hb = g_h1c + (size_t)b * HW_ * C1O;

    ull acc2[10];
    #pragma unroll
    for (int p = 0; p < 10; p++) acc2[p] = 0ull;

    #pragma unroll
    for (int pos = 0; pos < 9; pos++) {
        int yy = h + pos / 3 - 1, xx = w + pos % 3 - 1;
        bool valid = (yy >= 0 && yy < 64 && xx >= 0 && xx < 64);
        const float4* vp = (const float4*)(hb + (long long)(yy * 64 + xx) * 64);
        float4 z = make_float4(0.f, 0.f, 0.f, 0.f);
        #pragma unroll
        for (int c16 = 0; c16 < 4; c16++) {
            float4 v4 = valid ? vp[q * 4 + c16] : z;
            float vv[4] = {v4.x, v4.y, v4.z, v4.w};
            #pragma unroll
            for (int j = 0; j < 4; j++) {
                ull vd = dup2(vv[j]);
                const float* wb = &s_w[((q * 16 + c16 * 4 + j) * 9 + pos) * 20];
                #pragma unroll
                for (int o4 = 0; o4 < 5; o4++) {
                    ulonglong2 wq = *(const ulonglong2*)(wb + o4 * 4);
                    acc2[o4 * 2]     = fma2(wq.x, vd, acc2[o4 * 2]);
                    acc2[o4 * 2 + 1] = fma2(wq.y, vd, acc2[o4 * 2 + 1]);
                }
            }
        }
    }
    // reduce across q (4 lanes per location)
    #pragma unroll
    for (int p = 0; p < 9; p++) {
        acc2[p] = add2(acc2[p], __shfl_xor_sync(0xffffffffu, acc2[p], 1));
        acc2[p] = add2(acc2[p], __shfl_xor_sync(0xffffffffu, acc2[p], 2));
    }
    if (q == 0) {
        #pragma unroll
        for (int p = 0; p < 9; p++) {
            float2 f = unpack2(acc2[p]);
            g_off2[(size_t)(b * 18 + 2 * p)     * HW_ + hw] = f.x + s_b[2 * p];
            g_off2[(size_t)(b * 18 + 2 * p + 1) * HW_ + hw] = f.y + s_b[2 * p + 1];
        }
    }
}

// ---------------- K3: deform conv2 + bn2 + relu + pooled partials ----------
#define K3_SMEM_WORDS (32*577 + 32*132 + 288 + 288 + 288 + 288 + 128 + 128)
#define K3_SMEM_BYTES (K3_SMEM_WORDS * 4)

__global__ void __launch_bounds__(256)
k3_deform2(const float* __restrict__ cb,
           const float* __restrict__ g2, const float* __restrict__ be2,
           const float* __restrict__ m2, const float* __restrict__ v2)
{
    extern __shared__ float smem[];
    float* v_s     = smem;                  // [loc][e] padded: loc*577+e
    float* s_wt    = v_s + 32 * 577;        // [e_l][co] row stride 132
    float* s_wy    = s_wt + 32 * 132;       // 288
    float* s_wx    = s_wy + 288;            // 288
    int*   s_y0    = (int*)(s_wx + 288);    // 288
    int*   s_x0    = s_y0 + 288;            // 288
    float* s_scale = (float*)(s_x0 + 288);  // 128
    float* s_bias  = s_scale + 128;         // 128

    int tid = threadIdx.x;
    int blk = blockIdx.x;
    int wt = blk & 1, h = (blk >> 1) & 63, b = blk >> 7;
    int w0 = wt * 32;

    if (tid < 128) {
        float sc = g2[tid] * rsqrtf(v2[tid] + 1e-5f);
        s_scale[tid] = sc;
        s_bias[tid]  = be2[tid] + (cb[tid] - m2[tid]) * sc;
    }
    // phase A: offsets -> sampling coords
    for (int t = tid; t < 288; t += 256) {
        int tap = t >> 5, loc = t & 31;
        int w = w0 + loc;
        float dy = g_off2[(size_t)(b * 18 + tap * 2)     * HW_ + h * 64 + w];
        float dx = g_off2[(size_t)(b * 18 + tap * 2 + 1) * HW_ + h * 64 + w];
        float py = (float)(h + tap / 3 - 1) + dy;
        float px = (float)(w + tap % 3 - 1) + dx;
        float y0f = floorf(py), x0f = floorf(px);
        s_y0[t] = (int)y0f; s_x0[t] = (int)x0f;
        s_wy[t] = py - y0f; s_wx[t] = px - x0f;
    }
    __syncthreads();

    // phase B: bilinear sampling, channel-last vectorized
    const float* hb = g_h1c + (size_t)b * HW_ * C1O;
    for (int st = tid; st < 4608; st += 256) {          // 288 tasks x 16 ci-chunks
        int task = st >> 4, t16 = st & 15;
        int tap = task >> 5, loc = task & 31;
        int y0 = s_y0[task], x0 = s_x0[task];
        float wy = s_wy[task], wx = s_wx[task];
        float w00 = (1.f - wy) * (1.f - wx), w01 = (1.f - wy) * wx;
        float w10 = wy * (1.f - wx),          w11 = wy * wx;
        bool vy0 = ((unsigned)y0 < 64u), vy1 = ((unsigned)(y0 + 1) < 64u);
        bool vx0 = ((unsigned)x0 < 64u), vx1 = ((unsigned)(x0 + 1) < 64u);
        int ci = t16 * 4;
        float4 z = make_float4(0.f, 0.f, 0.f, 0.f);
        const float* p00 = hb + ((long long)y0 * 64 + x0) * 64 + ci;
        float4 c00 = (vy0 && vx0) ? *(const float4*)(p00)            : z;
        float4 c01 = (vy0 && vx1) ? *(const float4*)(p00 + 64)       : z;
        float4 c10 = (vy1 && vx0) ? *(const float4*)(p00 + 4096)     : z;
        float4 c11 = (vy1 && vx1) ? *(const float4*)(p00 + 4096 + 64): z;
        float* vd = &v_s[loc * 577 + ci * 9 + tap];
        vd[0]  = c00.x * w00 + c01.x * w01 + c10.x * w10 + c11.x * w11;
        vd[9]  = c00.y * w00 + c01.y * w01 + c10.y * w10 + c11.y * w11;
        vd[18] = c00.z * w00 + c01.z * w01 + c10.z * w10 + c11.z * w11;
        vd[27] = c00.w * w00 + c01.w * w01 + c10.w * w10 + c11.w * w11;
    }
    __syncthreads();

    // phase C: GEMM 128co x 32loc via f32x2. Tile: 8 co x 2 loc per thread.
    int lg = tid & 15, cog = tid >> 4;
    const float* vrow0 = &v_s[(2 * lg) * 577];
    const float* vrow1 = vrow0 + 577;

    ull acc2[4][2];
    #pragma unroll
    for (int r = 0; r < 4; r++) { acc2[r][0] = 0ull; acc2[r][1] = 0ull; }

    for (int et = 0; et < 18; et++) {
        #pragma unroll
        for (int k = 0; k < 16; k++) {
            int idx = tid + k * 256;                  // 0..4095
            int e_l = idx >> 7, co = idx & 127;
            s_wt[e_l * 132 + co] = g_wT[(et * 32 + e_l) * 128 + co];
        }
        __syncthreads();
        #pragma unroll 4
        for (int e_l = 0; e_l < 32; e_l++) {
            int e = et * 32 + e_l;
            const float* wrow = &s_wt[e_l * 132 + cog * 8];
            ulonglong2 wa = *(const ulonglong2*)(wrow);
            ulonglong2 wb = *(const ulonglong2*)(wrow + 4);
            ull v0 = dup2(vrow0[e]);
            ull v1 = dup2(vrow1[e]);
            acc2[0][0] = fma2(wa.x, v0, acc2[0][0]);
            acc2[0][1] = fma2(wa.x, v1, acc2[0][1]);
            acc2[1][0] = fma2(wa.y, v0, acc2[1][0]);
            acc2[1][1] = fma2(wa.y, v1, acc2[1][1]);
            acc2[2][0] = fma2(wb.x, v0, acc2[2][0]);
            acc2[2][1] = fma2(wb.x, v1, acc2[2][1]);
            acc2[3][0] = fma2(wb.y, v0, acc2[3][0]);
            acc2[3][1] = fma2(wb.y, v1, acc2[3][1]);
        }
        __syncthreads();
    }

    // epilogue: bn + relu + partial pooled sum (deterministic)
    #pragma unroll
    for (int c4 = 0; c4 < 4; c4++) {
        int co0 = cog * 8 + 2 * c4;
        float sc0 = s_scale[co0],     bi0 = s_bias[co0];
        float sc1 = s_scale[co0 + 1], bi1 = s_bias[co0 + 1];
        float2 a0 = unpack2(acc2[c4][0]);
        float2 a1 = unpack2(acc2[c4][1]);
        float r0 = fmaxf(a0.x * sc0 + bi0, 0.f) + fmaxf(a1.x * sc0 + bi0, 0.f);
        float r1 = fmaxf(a0.y * sc1 + bi1, 0.f) + fmaxf(a1.y * sc1 + bi1, 0.f);
        #pragma unroll
        for (int m = 1; m < 16; m <<= 1) {
            r0 += __shfl_xor_sync(0xffffffffu, r0, m);
            r1 += __shfl_xor_sync(0xffffffffu, r1, m);
        }
        if (lg == 0) {
            g_partial[(size_t)blk * 128 + co0]     = r0;
            g_partial[(size_t)blk * 128 + co0 + 1] = r1;
        }
    }
}

// ---------------- K4: reduce partials + fc1 + relu + fc2 --------------------
__global__ void __launch_bounds__(256)
k4_fc(const float* __restrict__ fc1w, const float* __restrict__ fc1b,
      const float* __restrict__ fc2w, const float* __restrict__ fc2b,
      float* __restrict__ out)
{
    __shared__ float red[256];
    __shared__ float sp[128];
    __shared__ float hid[256];
    int b = blockIdx.x, tid = threadIdx.x;
    int co = tid & 127, half = tid >> 7;
    const float* pb = g_partial + (size_t)b * 128 * 128;
    float s = 0.f;
    for (int i = half * 64; i < half * 64 + 64; i++)
        s += pb[(size_t)i * 128 + co];
    red[tid] = s;
    __syncthreads();
    if (tid < 128) sp[tid] = (red[tid] + red[tid + 128]) * (1.f / 4096.f);
    __syncthreads();
    {
        float a = fc1b[tid];
        #pragma unroll 8
        for (int j = 0; j < 128; j++) a += fc1w[tid * 128 + j] * sp[j];
        hid[tid] = fmaxf(a, 0.f);
    }
    __syncthreads();
    if (tid < 200) {
        float a = fc2b[tid];
        #pragma unroll 8
        for (int j = 0; j < 256; j++) a += fc2w[tid * 256 + j] * hid[j];
        out[b * 200 + tid] = a;
    }
}

// ---------------- launch -----------------------------------------------------
extern "C" void kernel_launch(void* const* d_in, const int* in_sizes, int n_in,
                              void* d_out, int out_size)
{
    const float* x    = (const float*)d_in[0];
    const float* o1w  = (const float*)d_in[1];
    const float* o1b  = (const float*)d_in[2];
    const float* c1w  = (const float*)d_in[3];
    const float* c1b  = (const float*)d_in[4];
    const float* g1   = (const float*)d_in[5];
    const float* be1  = (const float*)d_in[6];
    const float* m1   = (const float*)d_in[7];
    const float* v1   = (const float*)d_in[8];
    const float* o2w  = (const float*)d_in[9];
    const float* o2b  = (const float*)d_in[10];
    const float* c2w  = (const float*)d_in[11];
    const float* c2b  = (const float*)d_in[12];
    const float* g2   = (const float*)d_in[13];
    const float* be2  = (const float*)d_in[14];
    const float* m2   = (const float*)d_in[15];
    const float* v2   = (const float*)d_in[16];
    const float* f1w  = (const float*)d_in[17];
    const float* f1b  = (const float*)d_in[18];
    const float* f2w  = (const float*)d_in[19];
    const float* f2b  = (const float*)d_in[20];
    float* out = (float*)d_out;

    cudaFuncSetAttribute(k3_deform2, cudaFuncAttributeMaxDynamicSharedMemorySize, K3_SMEM_BYTES);

    k0_transpose<<<288, 256>>>(c2w);
    k1_layer1<<<1024, 128>>>(x, o1w, o1b, c1w, c1b, g1, be1, m1, v1);
    k2_off2<<<2048, 256>>>(o2w, o2b);
    k3_deform2<<<4096, 256, K3_SMEM_BYTES>>>(c2b, g2, be2, m2, v2);
    k4_fc<<<32, 256>>>(f1w, f1b, f2w, f2b, out);
}

// round 3
// speedup vs baseline: 1.4407x; 1.4407x over previous
#include <cuda_runtime.h>
#include <math.h>

// ---------------- scratch (device globals; no cudaMalloc allowed) ----------
#define B_   32
#define HW_  4096           // 64*64
#define C1O  64
#define C2O  128

__device__ float g_h1c[(size_t)B_ * HW_ * C1O];        // channel-last h1: [b][h][w][c]
__device__ float g_off2[(size_t)B_ * 18 * HW_];        // offsets layer2
__device__ float g_partial[(size_t)2048 * C2O];        // per-block pooled partials
__device__ float g_wT[576 * 128];                      // transposed conv2 weights [e][co]

// ---------------- packed f32x2 helpers --------------------------------------
typedef unsigned long long ull;

__device__ __forceinline__ ull fma2(ull a, ull b, ull c) {
    ull d;
    asm("fma.rn.f32x2 %0, %1, %2, %3;" : "=l"(d) : "l"(a), "l"(b), "l"(c));
    return d;
}
__device__ __forceinline__ ull dup2(float v) {
    ull d;
    unsigned r = __float_as_uint(v);
    asm("mov.b64 %0, {%1, %1};" : "=l"(d) : "r"(r));
    return d;
}
__device__ __forceinline__ float2 unpack2(ull v) {
    unsigned lo, hi;
    asm("mov.b64 {%0, %1}, %2;" : "=r"(lo), "=r"(hi) : "l"(v));
    return make_float2(__uint_as_float(lo), __uint_as_float(hi));
}

// ---------------- K0: transpose conv2 weights -------------------------------
__global__ void k0_transpose(const float* __restrict__ cw)
{
    int idx = blockIdx.x * 256 + threadIdx.x;
    if (idx >= 576 * 128) return;
    int co = idx & 127, e = idx >> 7;
    g_wT[e * 128 + co] = cw[co * 576 + e];
}

// ---------------- K1: offset1 conv + deform conv1 + bn1 + relu -------------
__global__ void __launch_bounds__(128)
k1_layer1(const float* __restrict__ x,
          const float* __restrict__ ow, const float* __restrict__ ob,
          const float* __restrict__ cw, const float* __restrict__ cb,
          const float* __restrict__ g1, const float* __restrict__ be1,
          const float* __restrict__ m1, const float* __restrict__ v1)
{
    __shared__ float s_ow[486];     // 18*27
    __shared__ float s_cw[1728];    // 64*27
    __shared__ float s_ob[18];
    __shared__ float s_scale[64], s_bias[64];
    __shared__ float s_out[128 * 65];

    int tid = threadIdx.x;
    for (int i = tid; i < 486; i += 128)  s_ow[i] = ow[i];
    for (int i = tid; i < 1728; i += 128) s_cw[i] = cw[i];
    if (tid < 18) s_ob[tid] = ob[tid];
    if (tid < 64) {
        float sc = g1[tid] * rsqrtf(v1[tid] + 1e-5f);
        s_scale[tid] = sc;
        s_bias[tid]  = be1[tid] + (cb[tid] - m1[tid]) * sc;
    }
    __syncthreads();

    int lin = blockIdx.x * 128 + tid;
    int b = lin >> 12, hw = lin & 4095, h = hw >> 6, w = hw & 63;
    const float* xb = x + (size_t)b * 3 * 4096;

    float xwin[27];
    #pragma unroll
    for (int ci = 0; ci < 3; ci++)
        #pragma unroll
        for (int kh = 0; kh < 3; kh++)
            #pragma unroll
            for (int kw = 0; kw < 3; kw++) {
                int yy = h + kh - 1, xx = w + kw - 1;
                float val = 0.f;
                if (yy >= 0 && yy < 64 && xx >= 0 && xx < 64)
                    val = xb[ci * 4096 + yy * 64 + xx];
                xwin[ci * 9 + kh * 3 + kw] = val;
            }

    float off[18];
    #pragma unroll
    for (int c = 0; c < 18; c++) {
        float a = s_ob[c];
        #pragma unroll
        for (int j = 0; j < 27; j++) a += xwin[j] * s_ow[c * 27 + j];
        off[c] = a;
    }

    float v[27];
    #pragma unroll
    for (int tap = 0; tap < 9; tap++) {
        float py = (float)(h + tap / 3 - 1) + off[tap * 2];
        float px = (float)(w + tap % 3 - 1) + off[tap * 2 + 1];
        float y0f = floorf(py), x0f = floorf(px);
        int y0 = (int)y0f, x0 = (int)x0f;
        float wy = py - y0f, wx = px - x0f;
        float w00 = (1.f - wy) * (1.f - wx), w01 = (1.f - wy) * wx;
        float w10 = wy * (1.f - wx),         w11 = wy * wx;
        bool vy0 = ((unsigned)y0 < 64u), vy1 = ((unsigned)(y0 + 1) < 64u);
        bool vx0 = ((unsigned)x0 < 64u), vx1 = ((unsigned)(x0 + 1) < 64u);
        long long i00 = (long long)y0 * 64 + x0;
        #pragma unroll
        for (int ci = 0; ci < 3; ci++) {
            const float* p = xb + ci * 4096;
            float c00 = (vy0 && vx0) ? p[i00]      : 0.f;
            float c01 = (vy0 && vx1) ? p[i00 + 1]  : 0.f;
            float c10 = (vy1 && vx0) ? p[i00 + 64] : 0.f;
            float c11 = (vy1 && vx1) ? p[i00 + 65] : 0.f;
            v[ci * 9 + tap] = c00 * w00 + c01 * w01 + c10 * w10 + c11 * w11;
        }
    }

    #pragma unroll 4
    for (int co = 0; co < 64; co++) {
        float a = 0.f;
        #pragma unroll
        for (int j = 0; j < 27; j++) a += v[j] * s_cw[co * 27 + j];
        float val = a * s_scale[co] + s_bias[co];
        s_out[tid * 65 + co] = fmaxf(val, 0.f);
    }
    __syncthreads();

    size_t base = (size_t)blockIdx.x * 128 * 64;
    for (int i = tid; i < 8192; i += 128)
        g_h1c[base + i] = s_out[(i >> 6) * 65 + (i & 63)];
}

// ---------------- K2: offset2 conv (64 -> 18), 1 loc/thread, f32x2 ----------
__global__ void __launch_bounds__(256)
k2_off2(const float* __restrict__ w2, const float* __restrict__ b2)
{
    __shared__ float s_w[576 * 20];   // transposed, padded: [(ci*9+pos)][o(20)]
    __shared__ float s_b[18];
    int tid = threadIdx.x;
    for (int i = tid; i < 18 * 576; i += 256) {
        int o = i / 576, cp = i % 576;
        s_w[cp * 20 + o] = w2[i];
    }
    for (int i = tid; i < 576; i += 256) { s_w[i * 20 + 18] = 0.f; s_w[i * 20 + 19] = 0.f; }
    if (tid < 18) s_b[tid] = b2[tid];
    __syncthreads();

    int lin = blockIdx.x * 256 + tid;
    int b = lin >> 12, hw = lin & 4095, h = hw >> 6, w = hw & 63;
    const float* hb = g_h1c + (size_t)b * HW_ * C1O;

    ull acc2[10];
    #pragma unroll
    for (int p = 0; p < 10; p++) acc2[p] = 0ull;

    #pragma unroll
    for (int pos = 0; pos < 9; pos++) {
        int yy = h + pos / 3 - 1, xx = w + pos % 3 - 1;
        bool valid = (yy >= 0 && yy < 64 && xx >= 0 && xx < 64);
        const float4* vp = (const float4*)(hb + (long long)(yy * 64 + xx) * 64);
        float4 z = make_float4(0.f, 0.f, 0.f, 0.f);
        #pragma unroll 1
        for (int c4 = 0; c4 < 16; c4++) {
            float4 v4 = valid ? vp[c4] : z;
            float vv[4] = {v4.x, v4.y, v4.z, v4.w};
            #pragma unroll
            for (int j = 0; j < 4; j++) {
                ull vd = dup2(vv[j]);
                const float* wb = &s_w[((c4 * 4 + j) * 9 + pos) * 20];
                #pragma unroll
                for (int o4 = 0; o4 < 5; o4++) {
                    ulonglong2 wq = *(const ulonglong2*)(wb + o4 * 4);
                    acc2[o4 * 2]     = fma2(wq.x, vd, acc2[o4 * 2]);
                    acc2[o4 * 2 + 1] = fma2(wq.y, vd, acc2[o4 * 2 + 1]);
                }
            }
        }
    }
    #pragma unroll
    for (int p = 0; p < 9; p++) {
        float2 f = unpack2(acc2[p]);
        g_off2[(size_t)(b * 18 + 2 * p)     * HW_ + hw] = f.x + s_b[2 * p];
        g_off2[(size_t)(b * 18 + 2 * p + 1) * HW_ + hw] = f.y + s_b[2 * p + 1];
    }
}

// ---------------- K3: deform conv2 + bn2 + relu + pooled partials ----------
// CTA = (b, h): 128 co x 64 loc. 256 threads: 16 co-groups x 16 loc-groups.
// v_s[e][loc] stride 68; thread tile 8co x 4loc, co packed in f32x2 pairs.
#define VS_STRIDE 68
#define K3_SMEM_WORDS (576*VS_STRIDE + 32*128 + 4*576 + 256)
#define K3_SMEM_BYTES (K3_SMEM_WORDS * 4)

__global__ void __launch_bounds__(256)
k3_deform2(const float* __restrict__ cb,
           const float* __restrict__ g2, const float* __restrict__ be2,
           const float* __restrict__ m2, const float* __restrict__ v2)
{
    extern __shared__ float smem[];
    float* v_s     = smem;                          // [576][68]
    float* s_wt    = v_s + 576 * VS_STRIDE;         // [32][128]
    float* s_wy    = s_wt + 32 * 128;               // 576
    float* s_wx    = s_wy + 576;                    // 576
    int*   s_y0    = (int*)(s_wx + 576);            // 576
    int*   s_x0    = s_y0 + 576;                    // 576
    float* s_scale = (float*)(s_x0 + 576);          // 128
    float* s_bias  = s_scale + 128;                 // 128

    int tid = threadIdx.x;
    int blk = blockIdx.x;
    int h = blk & 63, b = blk >> 6;

    if (tid < 128) {
        float sc = g2[tid] * rsqrtf(v2[tid] + 1e-5f);
        s_scale[tid] = sc;
        s_bias[tid]  = be2[tid] + (cb[tid] - m2[tid]) * sc;
    }
    // phase A: offsets -> sampling coords (576 = 9 taps x 64 locs)
    for (int t = tid; t < 576; t += 256) {
        int tap = t >> 6, loc = t & 63;
        float dy = g_off2[(size_t)(b * 18 + tap * 2)     * HW_ + h * 64 + loc];
        float dx = g_off2[(size_t)(b * 18 + tap * 2 + 1) * HW_ + h * 64 + loc];
        float py = (float)(h + tap / 3 - 1) + dy;
        float px = (float)(loc + tap % 3 - 1) + dx;
        float y0f = floorf(py), x0f = floorf(px);
        s_y0[t] = (int)y0f; s_x0[t] = (int)x0f;
        s_wy[t] = py - y0f; s_wx[t] = px - x0f;
    }
    __syncthreads();

    // phase B: bilinear sampling -> v_s[e][loc]
    const float* hb = g_h1c + (size_t)b * HW_ * C1O;
    for (int st = tid; st < 9216; st += 256) {        // 576 tasks x 16 ci-chunks
        int task = st >> 4, t16 = st & 15;
        int tap = task >> 6, loc = task & 63;
        int y0 = s_y0[task], x0 = s_x0[task];
        float wy = s_wy[task], wx = s_wx[task];
        float w00 = (1.f - wy) * (1.f - wx), w01 = (1.f - wy) * wx;
        float w10 = wy * (1.f - wx),          w11 = wy * wx;
        bool vy0 = ((unsigned)y0 < 64u), vy1 = ((unsigned)(y0 + 1) < 64u);
        bool vx0 = ((unsigned)x0 < 64u), vx1 = ((unsigned)(x0 + 1) < 64u);
        int ci = t16 * 4;
        float4 z = make_float4(0.f, 0.f, 0.f, 0.f);
        const float* p00 = hb + ((long long)y0 * 64 + x0) * 64 + ci;
        float4 c00 = (vy0 && vx0) ? *(const float4*)(p00)            : z;
        float4 c01 = (vy0 && vx1) ? *(const float4*)(p00 + 64)       : z;
        float4 c10 = (vy1 && vx0) ? *(const float4*)(p00 + 4096)     : z;
        float4 c11 = (vy1 && vx1) ? *(const float4*)(p00 + 4096 + 64): z;
        v_s[(ci * 9 + tap) * VS_STRIDE + loc]       = c00.x * w00 + c01.x * w01 + c10.x * w10 + c11.x * w11;
        v_s[((ci + 1) * 9 + tap) * VS_STRIDE + loc] = c00.y * w00 + c01.y * w01 + c10.y * w10 + c11.y * w11;
        v_s[((ci + 2) * 9 + tap) * VS_STRIDE + loc] = c00.z * w00 + c01.z * w01 + c10.z * w10 + c11.z * w11;
        v_s[((ci + 3) * 9 + tap) * VS_STRIDE + loc] = c00.w * w00 + c01.w * w01 + c10.w * w10 + c11.w * w11;
    }
    __syncthreads();

    // phase C: 128co x 64loc GEMM. Thread tile: 8co (4 f32x2 pairs) x 4loc.
    int lg = tid & 15, cog = tid >> 4;          // loc-group, co-group
    ull acc[4][4];                               // [copair][loc]
    #pragma unroll
    for (int p = 0; p < 4; p++)
        #pragma unroll
        for (int l = 0; l < 4; l++) acc[p][l] = 0ull;

    for (int et = 0; et < 18; et++) {
        #pragma unroll
        for (int k = 0; k < 16; k++) {
            int idx = k * 256 + tid;             // 0..4095
            int e_l = idx >> 7, co = idx & 127;
            s_wt[e_l * 128 + co] = g_wT[(et * 32 + e_l) * 128 + co];
        }
        __syncthreads();
        #pragma unroll 2
        for (int e_l = 0; e_l < 32; e_l++) {
            const float* wrow = &s_wt[e_l * 128 + cog * 8];
            ulonglong2 w01 = *(const ulonglong2*)(wrow);
            ulonglong2 w23 = *(const ulonglong2*)(wrow + 4);
            const float* arow = &v_s[(et * 32 + e_l) * VS_STRIDE + lg * 4];
            float4 a = *(const float4*)(arow);
            ull a0 = dup2(a.x), a1 = dup2(a.y), a2 = dup2(a.z), a3 = dup2(a.w);
            acc[0][0] = fma2(w01.x, a0, acc[0][0]);
            acc[0][1] = fma2(w01.x, a1, acc[0][1]);
            acc[0][2] = fma2(w01.x, a2, acc[0][2]);
            acc[0][3] = fma2(w01.x, a3, acc[0][3]);
            acc[1][0] = fma2(w01.y, a0, acc[1][0]);
            acc[1][1] = fma2(w01.y, a1, acc[1][1]);
            acc[1][2] = fma2(w01.y, a2, acc[1][2]);
            acc[1][3] = fma2(w01.y, a3, acc[1][3]);
            acc[2][0] = fma2(w23.x, a0, acc[2][0]);
            acc[2][1] = fma2(w23.x, a1, acc[2][1]);
            acc[2][2] = fma2(w23.x, a2, acc[2][2]);
            acc[2][3] = fma2(w23.x, a3, acc[2][3]);
            acc[3][0] = fma2(w23.y, a0, acc[3][0]);
            acc[3][1] = fma2(w23.y, a1, acc[3][1]);
            acc[3][2] = fma2(w23.y, a2, acc[3][2]);
            acc[3][3] = fma2(w23.y, a3, acc[3][3]);
        }
        __syncthreads();
    }

    // epilogue: bn + relu + pooled partial over the 64 locs (deterministic)
    #pragma unroll
    for (int p = 0; p < 4; p++) {
        int co0 = cog * 8 + 2 * p;
        float sc0 = s_scale[co0],     bi0 = s_bias[co0];
        float sc1 = s_scale[co0 + 1], bi1 = s_bias[co0 + 1];
        float r0 = 0.f, r1 = 0.f;
        #pragma unroll
        for (int l = 0; l < 4; l++) {
            float2 a = unpack2(acc[p][l]);
            r0 += fmaxf(a.x * sc0 + bi0, 0.f);
            r1 += fmaxf(a.y * sc1 + bi1, 0.f);
        }
        #pragma unroll
        for (int m = 1; m < 16; m <<= 1) {
            r0 += __shfl_xor_sync(0xffffffffu, r0, m);
            r1 += __shfl_xor_sync(0xffffffffu, r1, m);
        }
        if (lg == 0) {
            g_partial[(size_t)blk * 128 + co0]     = r0;
            g_partial[(size_t)blk * 128 + co0 + 1] = r1;
        }
    }
}

// ---------------- K4: reduce partials + fc1 + relu + fc2 --------------------
__global__ void __launch_bounds__(256)
k4_fc(const float* __restrict__ fc1w, const float* __restrict__ fc1b,
      const float* __restrict__ fc2w, const float* __restrict__ fc2b,
      float* __restrict__ out)
{
    __shared__ float red[256];
    __shared__ float sp[128];
    __shared__ float hid[256];
    int b = blockIdx.x, tid = threadIdx.x;
    int co = tid & 127, half = tid >> 7;
    const float* pb = g_partial + (size_t)b * 64 * 128;
    float s = 0.f;
    for (int i = half * 32; i < half * 32 + 32; i++)
        s += pb[(size_t)i * 128 + co];
    red[tid] = s;
    __syncthreads();
    if (tid < 128) sp[tid] = (red[tid] + red[tid + 128]) * (1.f / 4096.f);
    __syncthreads();
    {
        float a = fc1b[tid];
        #pragma unroll 8
        for (int j = 0; j < 128; j++) a += fc1w[tid * 128 + j] * sp[j];
        hid[tid] = fmaxf(a, 0.f);
    }
    __syncthreads();
    if (tid < 200) {
        float a = fc2b[tid];
        #pragma unroll 8
        for (int j = 0; j < 256; j++) a += fc2w[tid * 256 + j] * hid[j];
        out[b * 200 + tid] = a;
    }
}

// ---------------- launch -----------------------------------------------------
extern "C" void kernel_launch(void* const* d_in, const int* in_sizes, int n_in,
                              void* d_out, int out_size)
{
    const float* x    = (const float*)d_in[0];
    const float* o1w  = (const float*)d_in[1];
    const float* o1b  = (const float*)d_in[2];
    const float* c1w  = (const float*)d_in[3];
    const float* c1b  = (const float*)d_in[4];
    const float* g1   = (const float*)d_in[5];
    const float* be1  = (const float*)d_in[6];
    const float* m1   = (const float*)d_in[7];
    const float* v1   = (const float*)d_in[8];
    const float* o2w  = (const float*)d_in[9];
    const float* o2b  = (const float*)d_in[10];
    const float* c2w  = (const float*)d_in[11];
    const float* c2b  = (const float*)d_in[12];
    const float* g2   = (const float*)d_in[13];
    const float* be2  = (const float*)d_in[14];
    const float* m2   = (const float*)d_in[15];
    const float* v2   = (const float*)d_in[16];
    const float* f1w  = (const float*)d_in[17];
    const float* f1b  = (const float*)d_in[18];
    const float* f2w  = (const float*)d_in[19];
    const float* f2b  = (const float*)d_in[20];
    float* out = (float*)d_out;

    cudaFuncSetAttribute(k3_deform2, cudaFuncAttributeMaxDynamicSharedMemorySize, K3_SMEM_BYTES);

    k0_transpose<<<288, 256>>>(c2w);
    k1_layer1<<<1024, 128>>>(x, o1w, o1b, c1w, c1b, g1, be1, m1, v1);
    k2_off2<<<512, 256>>>(o2w, o2b);
    k3_deform2<<<2048, 256, K3_SMEM_BYTES>>>(c2b, g2, be2, m2, v2);
    k4_fc<<<32, 256>>>(f1w, f1b, f2w, f2b, out);
}

// round 4
// speedup vs baseline: 1.8086x; 1.2553x over previous
#include <cuda_runtime.h>
#include <math.h>

// ---------------- scratch (device globals; no cudaMalloc allowed) ----------
#define B_   32
#define HW_  4096           // 64*64
#define C1O  64
#define C2O  128

__device__ float g_h1c[(size_t)B_ * HW_ * C1O];        // channel-last h1: [b][h][w][c]
__device__ float g_off2[(size_t)B_ * 18 * HW_];        // offsets layer2
__device__ float g_partial[(size_t)2048 * C2O];        // per-block pooled partials
__device__ float g_wT[576 * 128];                      // transposed conv2 weights [e][co]

// ---------------- packed f32x2 helpers --------------------------------------
typedef unsigned long long ull;

__device__ __forceinline__ ull fma2(ull a, ull b, ull c) {
    ull d;
    asm("fma.rn.f32x2 %0, %1, %2, %3;" : "=l"(d) : "l"(a), "l"(b), "l"(c));
    return d;
}
__device__ __forceinline__ ull dup2(float v) {
    ull d;
    unsigned r = __float_as_uint(v);
    asm("mov.b64 %0, {%1, %1};" : "=l"(d) : "r"(r));
    return d;
}
__device__ __forceinline__ float2 unpack2(ull v) {
    unsigned lo, hi;
    asm("mov.b64 {%0, %1}, %2;" : "=r"(lo), "=r"(hi) : "l"(v));
    return make_float2(__uint_as_float(lo), __uint_as_float(hi));
}

// ---------------- K0: transpose conv2 weights -------------------------------
__global__ void k0_transpose(const float* __restrict__ cw)
{
    int idx = blockIdx.x * 256 + threadIdx.x;
    if (idx >= 576 * 128) return;
    int co = idx & 127, e = idx >> 7;
    g_wT[e * 128 + co] = cw[co * 576 + e];
}

// ---------------- K1: offset1 conv + deform conv1 + bn1 + relu -------------
__global__ void __launch_bounds__(128)
k1_layer1(const float* __restrict__ x,
          const float* __restrict__ ow, const float* __restrict__ ob,
          const float* __restrict__ cw, const float* __restrict__ cb,
          const float* __restrict__ g1, const float* __restrict__ be1,
          const float* __restrict__ m1, const float* __restrict__ v1)
{
    __shared__ float s_ow[486];     // 18*27
    __shared__ float s_cw[1728];    // 64*27
    __shared__ float s_ob[18];
    __shared__ float s_scale[64], s_bias[64];
    __shared__ float s_out[128 * 65];

    int tid = threadIdx.x;
    for (int i = tid; i < 486; i += 128)  s_ow[i] = ow[i];
    for (int i = tid; i < 1728; i += 128) s_cw[i] = cw[i];
    if (tid < 18) s_ob[tid] = ob[tid];
    if (tid < 64) {
        float sc = g1[tid] * rsqrtf(v1[tid] + 1e-5f);
        s_scale[tid] = sc;
        s_bias[tid]  = be1[tid] + (cb[tid] - m1[tid]) * sc;
    }
    __syncthreads();

    int lin = blockIdx.x * 128 + tid;
    int b = lin >> 12, hw = lin & 4095, h = hw >> 6, w = hw & 63;
    const float* xb = x + (size_t)b * 3 * 4096;

    float xwin[27];
    #pragma unroll
    for (int ci = 0; ci < 3; ci++)
        #pragma unroll
        for (int kh = 0; kh < 3; kh++)
            #pragma unroll
            for (int kw = 0; kw < 3; kw++) {
                int yy = h + kh - 1, xx = w + kw - 1;
                float val = 0.f;
                if (yy >= 0 && yy < 64 && xx >= 0 && xx < 64)
                    val = xb[ci * 4096 + yy * 64 + xx];
                xwin[ci * 9 + kh * 3 + kw] = val;
            }

    float off[18];
    #pragma unroll
    for (int c = 0; c < 18; c++) {
        float a = s_ob[c];
        #pragma unroll
        for (int j = 0; j < 27; j++) a += xwin[j] * s_ow[c * 27 + j];
        off[c] = a;
    }

    float v[27];
    #pragma unroll
    for (int tap = 0; tap < 9; tap++) {
        float py = (float)(h + tap / 3 - 1) + off[tap * 2];
        float px = (float)(w + tap % 3 - 1) + off[tap * 2 + 1];
        float y0f = floorf(py), x0f = floorf(px);
        int y0 = (int)y0f, x0 = (int)x0f;
        float wy = py - y0f, wx = px - x0f;
        float w00 = (1.f - wy) * (1.f - wx), w01 = (1.f - wy) * wx;
        float w10 = wy * (1.f - wx),         w11 = wy * wx;
        bool vy0 = ((unsigned)y0 < 64u), vy1 = ((unsigned)(y0 + 1) < 64u);
        bool vx0 = ((unsigned)x0 < 64u), vx1 = ((unsigned)(x0 + 1) < 64u);
        long long i00 = (long long)y0 * 64 + x0;
        #pragma unroll
        for (int ci = 0; ci < 3; ci++) {
            const float* p = xb + ci * 4096;
            float c00 = (vy0 && vx0) ? p[i00]      : 0.f;
            float c01 = (vy0 && vx1) ? p[i00 + 1]  : 0.f;
            float c10 = (vy1 && vx0) ? p[i00 + 64] : 0.f;
            float c11 = (vy1 && vx1) ? p[i00 + 65] : 0.f;
            v[ci * 9 + tap] = c00 * w00 + c01 * w01 + c10 * w10 + c11 * w11;
        }
    }

    #pragma unroll 4
    for (int co = 0; co < 64; co++) {
        float a = 0.f;
        #pragma unroll
        for (int j = 0; j < 27; j++) a += v[j] * s_cw[co * 27 + j];
        float val = a * s_scale[co] + s_bias[co];
        s_out[tid * 65 + co] = fmaxf(val, 0.f);
    }
    __syncthreads();

    size_t base = (size_t)blockIdx.x * 128 * 64;
    for (int i = tid; i < 8192; i += 128)
        g_h1c[base + i] = s_out[(i >> 6) * 65 + (i & 63)];
}

// ---------------- K2: offset2 conv (64 -> 18), 1 loc/thread, f32x2 ----------
__global__ void __launch_bounds__(256)
k2_off2(const float* __restrict__ w2, const float* __restrict__ b2)
{
    __shared__ float s_w[576 * 20];   // transposed, padded: [(ci*9+pos)][o(20)]
    __shared__ float s_b[18];
    int tid = threadIdx.x;
    for (int i = tid; i < 18 * 576; i += 256) {
        int o = i / 576, cp = i % 576;
        s_w[cp * 20 + o] = w2[i];
    }
    for (int i = tid; i < 576; i += 256) { s_w[i * 20 + 18] = 0.f; s_w[i * 20 + 19] = 0.f; }
    if (tid < 18) s_b[tid] = b2[tid];
    __syncthreads();

    int lin = blockIdx.x * 256 + tid;
    int b = lin >> 12, hw = lin & 4095, h = hw >> 6, w = hw & 63;
    const float* hb = g_h1c + (size_t)b * HW_ * C1O;

    ull acc2[10];
    #pragma unroll
    for (int p = 0; p < 10; p++) acc2[p] = 0ull;

    #pragma unroll
    for (int pos = 0; pos < 9; pos++) {
        int yy = h + pos / 3 - 1, xx = w + pos % 3 - 1;
        bool valid = (yy >= 0 && yy < 64 && xx >= 0 && xx < 64);
        const float4* vp = (const float4*)(hb + (long long)(yy * 64 + xx) * 64);
        float4 z = make_float4(0.f, 0.f, 0.f, 0.f);
        #pragma unroll 1
        for (int c4 = 0; c4 < 16; c4++) {
            float4 v4 = valid ? vp[c4] : z;
            float vv[4] = {v4.x, v4.y, v4.z, v4.w};
            #pragma unroll
            for (int j = 0; j < 4; j++) {
                ull vd = dup2(vv[j]);
                const float* wb = &s_w[((c4 * 4 + j) * 9 + pos) * 20];
                #pragma unroll
                for (int o4 = 0; o4 < 5; o4++) {
                    ulonglong2 wq = *(const ulonglong2*)(wb + o4 * 4);
                    acc2[o4 * 2]     = fma2(wq.x, vd, acc2[o4 * 2]);
                    acc2[o4 * 2 + 1] = fma2(wq.y, vd, acc2[o4 * 2 + 1]);
                }
            }
        }
    }
    #pragma unroll
    for (int p = 0; p < 9; p++) {
        float2 f = unpack2(acc2[p]);
        g_off2[(size_t)(b * 18 + 2 * p)     * HW_ + hw] = f.x + s_b[2 * p];
        g_off2[(size_t)(b * 18 + 2 * p + 1) * HW_ + hw] = f.y + s_b[2 * p + 1];
    }
}

// ---------------- K3: deform conv2 + bn2 + relu + pooled partials ----------
// CTA = (b, h): 128 co x 64 loc, K split into 2 chunks of 288 (ci 0-31, 32-63).
// v_s[288][68]; thread tile 8co x 4loc. 2 CTAs/SM (smem ~105KB).
#define VS_STRIDE 68
#define CHUNK_E   288
#define K3_SMEM_WORDS (CHUNK_E*VS_STRIDE + 32*128 + 4*576 + 256)
#define K3_SMEM_BYTES (K3_SMEM_WORDS * 4)

__global__ void __launch_bounds__(256, 2)
k3_deform2(const float* __restrict__ cb,
           const float* __restrict__ g2, const float* __restrict__ be2,
           const float* __restrict__ m2, const float* __restrict__ v2)
{
    extern __shared__ float smem[];
    float* v_s     = smem;                          // [288][68]
    float* s_wt    = v_s + CHUNK_E * VS_STRIDE;     // [32][128]
    float* s_wy    = s_wt + 32 * 128;               // 576
    float* s_wx    = s_wy + 576;                    // 576
    int*   s_y0    = (int*)(s_wx + 576);            // 576
    int*   s_x0    = s_y0 + 576;                    // 576
    float* s_scale = (float*)(s_x0 + 576);          // 128
    float* s_bias  = s_scale + 128;                 // 128

    int tid = threadIdx.x;
    int blk = blockIdx.x;
    int h = blk & 63, b = blk >> 6;

    if (tid < 128) {
        float sc = g2[tid] * rsqrtf(v2[tid] + 1e-5f);
        s_scale[tid] = sc;
        s_bias[tid]  = be2[tid] + (cb[tid] - m2[tid]) * sc;
    }
    // phase A: offsets -> sampling coords (576 = 9 taps x 64 locs)
    for (int t = tid; t < 576; t += 256) {
        int tap = t >> 6, loc = t & 63;
        float dy = g_off2[(size_t)(b * 18 + tap * 2)     * HW_ + h * 64 + loc];
        float dx = g_off2[(size_t)(b * 18 + tap * 2 + 1) * HW_ + h * 64 + loc];
        float py = (float)(h + tap / 3 - 1) + dy;
        float px = (float)(loc + tap % 3 - 1) + dx;
        float y0f = floorf(py), x0f = floorf(px);
        s_y0[t] = (int)y0f; s_x0[t] = (int)x0f;
        s_wy[t] = py - y0f; s_wx[t] = px - x0f;
    }

    const float* hb = g_h1c + (size_t)b * HW_ * C1O;
    int lg = tid & 15, cog = tid >> 4;          // loc-group, co-group
    ull acc[4][4];                               // [copair][loc]
    #pragma unroll
    for (int p = 0; p < 4; p++)
        #pragma unroll
        for (int l = 0; l < 4; l++) acc[p][l] = 0ull;

    for (int chunk = 0; chunk < 2; chunk++) {
        __syncthreads();   // coords ready (chunk0) / v_s free for reuse (chunk1)

        // phase B: bilinear sampling of ci in [chunk*32, chunk*32+32)
        for (int st = tid; st < 4608; st += 256) {    // 576 tasks x 8 ci4-chunks
            int task = st >> 3, t8 = st & 7;
            int tap = task >> 6, loc = task & 63;
            int y0 = s_y0[task], x0 = s_x0[task];
            float wy = s_wy[task], wx = s_wx[task];
            float w00 = (1.f - wy) * (1.f - wx), w01 = (1.f - wy) * wx;
            float w10 = wy * (1.f - wx),          w11 = wy * wx;
            bool vy0 = ((unsigned)y0 < 64u), vy1 = ((unsigned)(y0 + 1) < 64u);
            bool vx0 = ((unsigned)x0 < 64u), vx1 = ((unsigned)(x0 + 1) < 64u);
            int ci_l = t8 * 4;
            float4 z = make_float4(0.f, 0.f, 0.f, 0.f);
            const float* p00 = hb + ((long long)y0 * 64 + x0) * 64 + chunk * 32 + ci_l;
            float4 c00 = (vy0 && vx0) ? *(const float4*)(p00)            : z;
            float4 c01 = (vy0 && vx1) ? *(const float4*)(p00 + 64)       : z;
            float4 c10 = (vy1 && vx0) ? *(const float4*)(p00 + 4096)     : z;
            float4 c11 = (vy1 && vx1) ? *(const float4*)(p00 + 4096 + 64): z;
            float* vd = v_s + (size_t)(ci_l * 9 + tap) * VS_STRIDE + loc;
            vd[0]               = c00.x * w00 + c01.x * w01 + c10.x * w10 + c11.x * w11;
            vd[9 * VS_STRIDE]   = c00.y * w00 + c01.y * w01 + c10.y * w10 + c11.y * w11;
            vd[18 * VS_STRIDE]  = c00.z * w00 + c01.z * w01 + c10.z * w10 + c11.z * w11;
            vd[27 * VS_STRIDE]  = c00.w * w00 + c01.w * w01 + c10.w * w10 + c11.w * w11;
        }
        __syncthreads();

        // phase C: GEMM over this chunk's 288 e's (9 weight tiles of 32)
        for (int et = 0; et < 9; et++) {
            #pragma unroll
            for (int k = 0; k < 16; k++) {
                int idx = k * 256 + tid;             // 0..4095
                int e_l = idx >> 7, co = idx & 127;
                s_wt[e_l * 128 + co] = g_wT[(chunk * CHUNK_E + et * 32 + e_l) * 128 + co];
            }
            __syncthreads();
            #pragma unroll 4
            for (int e_l = 0; e_l < 32; e_l++) {
                const float* wrow = &s_wt[e_l * 128 + cog * 8];
                ulonglong2 w01 = *(const ulonglong2*)(wrow);
                ulonglong2 w23 = *(const ulonglong2*)(wrow + 4);
                const float* arow = &v_s[(et * 32 + e_l) * VS_STRIDE + lg * 4];
                float4 a = *(const float4*)(arow);
                ull a0 = dup2(a.x), a1 = dup2(a.y), a2 = dup2(a.z), a3 = dup2(a.w);
                acc[0][0] = fma2(w01.x, a0, acc[0][0]);
                acc[0][1] = fma2(w01.x, a1, acc[0][1]);
                acc[0][2] = fma2(w01.x, a2, acc[0][2]);
                acc[0][3] = fma2(w01.x, a3, acc[0][3]);
                acc[1][0] = fma2(w01.y, a0, acc[1][0]);
                acc[1][1] = fma2(w01.y, a1, acc[1][1]);
                acc[1][2] = fma2(w01.y, a2, acc[1][2]);
                acc[1][3] = fma2(w01.y, a3, acc[1][3]);
                acc[2][0] = fma2(w23.x, a0, acc[2][0]);
                acc[2][1] = fma2(w23.x, a1, acc[2][1]);
                acc[2][2] = fma2(w23.x, a2, acc[2][2]);
                acc[2][3] = fma2(w23.x, a3, acc[2][3]);
                acc[3][0] = fma2(w23.y, a0, acc[3][0]);
                acc[3][1] = fma2(w23.y, a1, acc[3][1]);
                acc[3][2] = fma2(w23.y, a2, acc[3][2]);
                acc[3][3] = fma2(w23.y, a3, acc[3][3]);
            }
            __syncthreads();
        }
    }

    // epilogue: bn + relu + pooled partial over the 64 locs (deterministic)
    #pragma unroll
    for (int p = 0; p < 4; p++) {
        int co0 = cog * 8 + 2 * p;
        float sc0 = s_scale[co0],     bi0 = s_bias[co0];
        float sc1 = s_scale[co0 + 1], bi1 = s_bias[co0 + 1];
        float r0 = 0.f, r1 = 0.f;
        #pragma unroll
        for (int l = 0; l < 4; l++) {
            float2 a = unpack2(acc[p][l]);
            r0 += fmaxf(a.x * sc0 + bi0, 0.f);
            r1 += fmaxf(a.y * sc1 + bi1, 0.f);
        }
        #pragma unroll
        for (int m = 1; m < 16; m <<= 1) {
            r0 += __shfl_xor_sync(0xffffffffu, r0, m);
            r1 += __shfl_xor_sync(0xffffffffu, r1, m);
        }
        if (lg == 0) {
            g_partial[(size_t)blk * 128 + co0]     = r0;
            g_partial[(size_t)blk * 128 + co0 + 1] = r1;
        }
    }
}

// ---------------- K4: reduce partials + fc1 + relu + fc2 --------------------
__global__ void __launch_bounds__(256)
k4_fc(const float* __restrict__ fc1w, const float* __restrict__ fc1b,
      const float* __restrict__ fc2w, const float* __restrict__ fc2b,
      float* __restrict__ out)
{
    __shared__ float red[256];
    __shared__ float sp[128];
    __shared__ float hid[256];
    int b = blockIdx.x, tid = threadIdx.x;
    int co = tid & 127, half = tid >> 7;
    const float* pb = g_partial + (size_t)b * 64 * 128;
    float s = 0.f;
    for (int i = half * 32; i < half * 32 + 32; i++)
        s += pb[(size_t)i * 128 + co];
    red[tid] = s;
    __syncthreads();
    if (tid < 128) sp[tid] = (red[tid] + red[tid + 128]) * (1.f / 4096.f);
    __syncthreads();
    {
        float a = fc1b[tid];
        #pragma unroll 8
        for (int j = 0; j < 128; j++) a += fc1w[tid * 128 + j] * sp[j];
        hid[tid] = fmaxf(a, 0.f);
    }
    __syncthreads();
    if (tid < 200) {
        float a = fc2b[tid];
        #pragma unroll 8
        for (int j = 0; j < 256; j++) a += fc2w[tid * 256 + j] * hid[j];
        out[b * 200 + tid] = a;
    }
}

// ---------------- launch -----------------------------------------------------
extern "C" void kernel_launch(void* const* d_in, const int* in_sizes, int n_in,
                              void* d_out, int out_size)
{
    const float* x    = (const float*)d_in[0];
    const float* o1w  = (const float*)d_in[1];
    const float* o1b  = (const float*)d_in[2];
    const float* c1w  = (const float*)d_in[3];
    const float* c1b  = (const float*)d_in[4];
    const float* g1   = (const float*)d_in[5];
    const float* be1  = (const float*)d_in[6];
    const float* m1   = (const float*)d_in[7];
    const float* v1   = (const float*)d_in[8];
    const float* o2w  = (const float*)d_in[9];
    const float* o2b  = (const float*)d_in[10];
    const float* c2w  = (const float*)d_in[11];
    const float* c2b  = (const float*)d_in[12];
    const float* g2   = (const float*)d_in[13];
    const float* be2  = (const float*)d_in[14];
    const float* m2   = (const float*)d_in[15];
    const float* v2   = (const float*)d_in[16];
    const float* f1w  = (const float*)d_in[17];
    const float* f1b  = (const float*)d_in[18];
    const float* f2w  = (const float*)d_in[19];
    const float* f2b  = (const float*)d_in[20];
    float* out = (float*)d_out;

    cudaFuncSetAttribute(k3_deform2, cudaFuncAttributeMaxDynamicSharedMemorySize, K3_SMEM_BYTES);

    k0_transpose<<<288, 256>>>(c2w);
    k1_layer1<<<1024, 128>>>(x, o1w, o1b, c1w, c1b, g1, be1, m1, v1);
    k2_off2<<<512, 256>>>(o2w, o2b);
    k3_deform2<<<2048, 256, K3_SMEM_BYTES>>>(c2b, g2, be2, m2, v2);
    k4_fc<<<32, 256>>>(f1w, f1b, f2w, f2b, out);
}